// round 6
// baseline (speedup 1.0000x reference)
#include <cuda_runtime.h>
#include <math.h>

#define Bn 64
#define Tn 1024
#define Kn 128
#define NT 256
#define TAG_START 126
#define TAG_STOP  127
#define NEGV -10000.0f
#define LOG2E 1.4426950408889634f
#define LN2   0.6931471805599453f

__device__ float g_partial[Bn];
__device__ unsigned int g_count = 0;

#define FMA2(acc, x, y) \
    asm("fma.rn.f32x2 %0, %1, %2, %0;" : "+l"(acc) : "l"(x), "l"(y))

#define ADD2(dst, x, y) \
    asm("add.rn.f32x2 %0, %1, %2;" : "=l"(dst) : "l"(x), "l"(y))

#define PACK2(dst, lo, hi) \
    asm("mov.b64 %0, {%1, %2};" : "=l"(dst) : "f"(lo), "f"(hi))

#define UNPACK2(lo, hi, src) \
    asm("mov.b64 {%0, %1}, %2;" : "=f"(lo), "=f"(hi) : "l"(src))

__device__ __forceinline__ float ex2(float x) {
    float r; asm("ex2.approx.f32 %0, %1;" : "=f"(r) : "f"(x)); return r;
}
__device__ __forceinline__ float lg2(float x) {
    float r; asm("lg2.approx.f32 %0, %1;" : "=f"(r) : "f"(x)); return r;
}

__global__ __launch_bounds__(NT, 1) void crf_fwd_kernel(
    const float* __restrict__ feats,
    const int*   __restrict__ tags,
    const int*   __restrict__ lens,
    const float* __restrict__ trans,
    float*       __restrict__ out)
{
    const int b   = blockIdx.x;
    const int tid = threadIdx.x;
    const int w   = tid >> 5;
    const int l   = tid & 31;
    const int half = l >> 4;                 // 0: inputs [0,64), 1: [64,128)
    const int jj  = (w << 4) | (l & 15);     // output tag (pair (l, l^16) shares jj)
    const bool is_store = (l < 16);
    const bool is_renorm = (w == 0 && l == 16);   // computes w[0], publishes sv0

    const float* fb = feats + (size_t)b * Tn * Kn;
    const int*   tb = tags + b * Tn;
    const int    len = lens[b];

    __shared__ __align__(16) float eAs[2][Kn];
    __shared__ float sr[4];                  // lagged power-of-2 scales (ring)
    __shared__ float red[NT];
    __shared__ float sh_gold;
    __shared__ float sh_ci;
    __shared__ int   sh_last;

    // ---------------- gold score ----------------
    float gsum = 0.f;
    for (int t = tid; t < Tn; t += NT) {
        if (t < len)     gsum += fb[t * Kn + tb[t]];
        if (t < len - 1) gsum += trans[tb[t + 1] * Kn + tb[t]];
    }
    red[tid] = gsum;
    __syncthreads();
    #pragma unroll
    for (int s = NT / 2; s > 0; s >>= 1) {
        if (tid < s) red[tid] += red[tid + s];
        __syncthreads();
    }
    if (tid == 0) sh_gold = red[0];

    // ---------------- exp(trans) half-row into 32 regs ----------------
    unsigned long long eT2[32];
    const float* trow = trans + jj * Kn + half * 64;
    #pragma unroll
    for (int i = 0; i < 32; i++) {
        float e0 = ex2(trow[2 * i]     * LOG2E);
        float e1 = ex2(trow[2 * i + 1] * LOG2E);
        PACK2(eT2[i], e0, e1);
    }

    // ---------------- init ----------------
    float f0s = fb[TAG_START];
    float c2f = f0s * LOG2E;
    if (is_store) eAs[0][jj] = (jj == TAG_START) ? 1.f : 0.f;
    if (tid < 4)  sr[tid] = 1.f;             // slots read at t=1,2 must be 1
    if (tid == 0) sh_ci = 0.f;
    int c2i = 0;

    // depth-3 feat prefetch
    float fA = (1 < len) ? fb[1 * Kn + jj] : 0.f;
    float pA = (2 < len) ? fb[2 * Kn + jj] : 0.f;
    float pB = (3 < len) ? fb[3 * Kn + jj] : 0.f;
    float ef = ex2(fA * LOG2E);

    // ---------------- one forward step (macro-ish lambda) ----------------
    auto step = [&](int t, const float* __restrict__ src, float* __restrict__ dst) {
        float pC = (t + 3 < len) ? fb[(t + 3) * Kn + jj] : 0.f;
        float ef_next = ex2(pA * LOG2E);

        __syncthreads();
        float sc = sr[(t + 2) & 3];          // scale lagged 2 steps (exact 2^-e)
        float efs = ef * sc;
        if (is_renorm)                        // recover applied exponent from sc
            c2i += 127 - (__float_as_int(sc) >> 23);

        const ulonglong2* __restrict__ pV = (const ulonglong2*)(src + half * 64);
        unsigned long long acc0 = 0ull, acc1 = 0ull, acc2 = 0ull, acc3 = 0ull;
        #pragma unroll
        for (int i = 0; i < 8; i++) {
            ulonglong2 p = pV[i];
            FMA2(acc0, p.x, eT2[2 * i]);
            FMA2(acc1, p.y, eT2[2 * i + 1]);
        }
        #pragma unroll
        for (int i = 8; i < 16; i++) {
            ulonglong2 p = pV[i];
            FMA2(acc2, p.x, eT2[2 * i]);
            FMA2(acc3, p.y, eT2[2 * i + 1]);
        }
        unsigned long long s01, s23, sall;
        ADD2(s01, acc0, acc1);
        ADD2(s23, acc2, acc3);
        ADD2(sall, s01, s23);
        float lo, hi;
        UNPACK2(lo, hi, sall);
        float part = lo + hi;

        float other = __shfl_xor_sync(0xffffffffu, part, 16);
        float wv = (part + other) * efs;
        if (is_store) dst[jj] = wv;          // pre-barrier path ends here
        if (is_renorm) {                     // publish renorm for step t+2
            int e = (__float_as_int(wv) >> 23) - 127;
            sr[t & 3] = __int_as_float((127 - e) << 23);
        }
        ef = ef_next; pA = pB; pB = pC;
    };

    // ---------------- recursion, unrolled by 2 ----------------
    int t = 1;
    for (; t + 1 < len; t += 2) {
        step(t,     eAs[0], eAs[1]);
        step(t + 1, eAs[1], eAs[0]);
    }
    if (t < len) step(t, eAs[(t - 1) & 1], eAs[t & 1]);

    if (is_renorm) sh_ci = (float)c2i;

    // ---------------- terminal ----------------
    __syncthreads();
    red[tid] = is_store ? eAs[(len - 1) & 1][jj] : 0.f;
    __syncthreads();
    #pragma unroll
    for (int s = NT / 2; s > 0; s >>= 1) {
        if (tid < s) red[tid] += red[tid + s];
        __syncthreads();
    }
    if (tid == 0) {
        float forward = (sh_ci + c2f + lg2(red[0])) * LN2;
        g_partial[b] = forward - sh_gold;
        __threadfence();
        unsigned int f = atomicAdd(&g_count, 1);
        sh_last = (f == Bn - 1);
    }
    __syncthreads();

    if (sh_last) {
        __threadfence();
        red[tid] = (tid < Bn) ? g_partial[tid] : 0.f;
        __syncthreads();
        #pragma unroll
        for (int s = 32; s > 0; s >>= 1) {
            if (tid < s) red[tid] += red[tid + s];
            __syncthreads();
        }
        if (tid == 0) {
            out[0] = red[0] * (1.0f / Bn);
            g_count = 0;
        }
    }
}

extern "C" void kernel_launch(void* const* d_in, const int* in_sizes, int n_in,
                              void* d_out, int out_size)
{
    const float* feats = (const float*)d_in[0];
    const int*   tags  = (const int*)d_in[1];
    const int*   lens  = (const int*)d_in[2];
    const float* trans = (const float*)d_in[3];
    float* out = (float*)d_out;

    crf_fwd_kernel<<<Bn, NT>>>(feats, tags, lens, trans, out);
}